// round 4
// baseline (speedup 1.0000x reference)
#include <cuda_runtime.h>
#include <cuda_bf16.h>
#include <math.h>

#define Bn   128
#define Tn   200
#define Vn   50257
#define Hn   256
#define En   128
#define OOV  50
#define H2   512           // 2H
#define XD   640           // E + 2H
#define PV   (Vn + OOV)    // 50307

// ---------------- scratch (static device memory; no allocs) ----------------
__device__ float g_score[(size_t)Bn * Vn];   // score_g  (B, V)
__device__ float g_scorec[Bn * Tn];          // score_c  (B, T)
__device__ float g_max[Bn];
__device__ float g_invsum[Bn];

// ---------------------------------------------------------------------------
// Kernel A: GRU cell.  One block per batch row, 256 threads (= H).
// gru_in = [selective_read(512), emb[dec](128)]; handles step==0 path.
// ---------------------------------------------------------------------------
__global__ __launch_bounds__(256) void gru_kernel(
    const int* __restrict__ dec_in, const float* __restrict__ enc,
    const int* __restrict__ step,
    const float* __restrict__ prev_state, const float* __restrict__ sel,
    const float* __restrict__ emb,
    const float* __restrict__ W_ih, const float* __restrict__ W_hh,
    const float* __restrict__ b_ih, const float* __restrict__ b_hh,
    const float* __restrict__ Wi_w, const float* __restrict__ Wi_b,
    float* __restrict__ dh_out)
{
    __shared__ __align__(16) float xs[XD];
    __shared__ __align__(16) float hs[Hn];
    __shared__ __align__(16) float es[H2];

    const int b   = blockIdx.x;
    const int tid = threadIdx.x;
    const int stepv = step ? step[0] : 1;
    const int dec = dec_in[b];

    if (stepv != 0) {
        xs[tid]       = sel[b * H2 + tid];
        xs[tid + 256] = sel[b * H2 + tid + 256];
    } else {
        xs[tid] = 0.f; xs[tid + 256] = 0.f;
    }
    if (tid < En) xs[H2 + tid] = emb[(size_t)dec * En + tid];

    if (stepv != 0) {
        hs[tid] = prev_state[b * Hn + tid];
    } else {
        const float* el = enc + (size_t)b * Tn * H2 + (size_t)(Tn - 1) * H2;
        es[tid]       = el[tid];
        es[tid + 256] = el[tid + 256];
        __syncthreads();
        float acc = Wi_b[tid];
        const float4* wr = (const float4*)(Wi_w + (size_t)tid * H2);
        const float4* ev = (const float4*)es;
        #pragma unroll 8
        for (int k = 0; k < H2 / 4; k++) {
            float4 w = wr[k], e = ev[k];
            acc += w.x * e.x + w.y * e.y + w.z * e.z + w.w * e.w;
        }
        hs[tid] = acc;
    }
    __syncthreads();

    const int j = tid;
    float gir = b_ih[j], giz = b_ih[Hn + j], gin = b_ih[2 * Hn + j];
    {
        const float4* x4 = (const float4*)xs;
        const float4* r0 = (const float4*)(W_ih + (size_t)j * XD);
        const float4* r1 = (const float4*)(W_ih + (size_t)(Hn + j) * XD);
        const float4* r2 = (const float4*)(W_ih + (size_t)(2 * Hn + j) * XD);
        float a0 = 0.f, a1 = 0.f, a2 = 0.f;
        #pragma unroll 8
        for (int k = 0; k < XD / 4; k++) {
            float4 x = x4[k];
            float4 w0 = r0[k], w1 = r1[k], w2 = r2[k];
            a0 += w0.x * x.x + w0.y * x.y + w0.z * x.z + w0.w * x.w;
            a1 += w1.x * x.x + w1.y * x.y + w1.z * x.z + w1.w * x.w;
            a2 += w2.x * x.x + w2.y * x.y + w2.z * x.z + w2.w * x.w;
        }
        gir += a0; giz += a1; gin += a2;
    }
    float ghr = b_hh[j], ghz = b_hh[Hn + j], ghn = b_hh[2 * Hn + j];
    {
        const float4* h4 = (const float4*)hs;
        const float4* r0 = (const float4*)(W_hh + (size_t)j * Hn);
        const float4* r1 = (const float4*)(W_hh + (size_t)(Hn + j) * Hn);
        const float4* r2 = (const float4*)(W_hh + (size_t)(2 * Hn + j) * Hn);
        float a0 = 0.f, a1 = 0.f, a2 = 0.f;
        #pragma unroll 8
        for (int k = 0; k < Hn / 4; k++) {
            float4 x = h4[k];
            float4 w0 = r0[k], w1 = r1[k], w2 = r2[k];
            a0 += w0.x * x.x + w0.y * x.y + w0.z * x.z + w0.w * x.w;
            a1 += w1.x * x.x + w1.y * x.y + w1.z * x.z + w1.w * x.w;
            a2 += w2.x * x.x + w2.y * x.y + w2.z * x.z + w2.w * x.w;
        }
        ghr += a0; ghz += a1; ghn += a2;
    }
    float r = 1.f / (1.f + expf(-(gir + ghr)));
    float z = 1.f / (1.f + expf(-(giz + ghz)));
    float n = tanhf(gin + r * ghn);
    dh_out[b * Hn + j] = (1.f - z) * n + z * hs[j];
}

// ---------------------------------------------------------------------------
// Kernel B: score_g = dh(128x256) @ Wg^T(256xV) + Wg_b.
// Tiled SGEMM: BM=128 (all batches -> Wg read once from DRAM), BN=64, BK=32.
// 256 threads, 8x4 micro-tile per thread.
// ---------------------------------------------------------------------------
__global__ __launch_bounds__(256) void scoreg_kernel(
    const float* __restrict__ dh,
    const float* __restrict__ Wg, const float* __restrict__ Wgb)
{
    __shared__ float As[32 * 129];  // [k][b], padded
    __shared__ float Bs[32 * 65];   // [k][v], padded

    const int tid  = threadIdx.x;
    const int v0   = blockIdx.x * 64;
    const int row0 = (tid >> 4) * 8;   // batch base
    const int col0 = (tid & 15) * 4;   // v base within tile

    float acc[8][4];
    #pragma unroll
    for (int r = 0; r < 8; r++)
        #pragma unroll
        for (int c = 0; c < 4; c++) acc[r][c] = 0.f;

    for (int kt = 0; kt < 256; kt += 32) {
        for (int i = tid; i < 128 * 32; i += 256) {
            int bb = i >> 5, k = i & 31;
            As[k * 129 + bb] = dh[bb * 256 + kt + k];
        }
        for (int i = tid; i < 64 * 32; i += 256) {
            int v = i >> 5, k = i & 31;
            int vg = v0 + v;
            Bs[k * 65 + v] = (vg < Vn) ? Wg[(size_t)vg * 256 + kt + k] : 0.f;
        }
        __syncthreads();
        #pragma unroll
        for (int k = 0; k < 32; k++) {
            float a[8], bv[4];
            #pragma unroll
            for (int r = 0; r < 8; r++) a[r] = As[k * 129 + row0 + r];
            #pragma unroll
            for (int c = 0; c < 4; c++) bv[c] = Bs[k * 65 + col0 + c];
            #pragma unroll
            for (int r = 0; r < 8; r++)
                #pragma unroll
                for (int c = 0; c < 4; c++) acc[r][c] += a[r] * bv[c];
        }
        __syncthreads();
    }
    #pragma unroll
    for (int c = 0; c < 4; c++) {
        int vg = v0 + col0 + c;
        if (vg < Vn) {
            float bias = Wgb[vg];
            #pragma unroll
            for (int r = 0; r < 8; r++)
                g_score[(size_t)(row0 + r) * Vn + vg] = acc[r][c] + bias;
        }
    }
}

// ---------------------------------------------------------------------------
// Kernel C: enc_proj = tanh(enc @ Wc^T + Wc_b); score_c = tanh(enc_proj . dh)
//           + mask. Fused: P tile kept in registers, dh contraction in-epilogue.
// Block = (b, t-tile of 50). 320 threads, 5x8 micro-tile, K=512 in BK=32.
// ---------------------------------------------------------------------------
__global__ __launch_bounds__(320, 2) void scorec_kernel(
    const float* __restrict__ enc, const int* __restrict__ encIdx,
    const float* __restrict__ Wc, const float* __restrict__ Wcb,
    const float* __restrict__ dh)
{
    __shared__ float dhs[256];
    __shared__ float Es[32 * 51];    // [k][t]
    __shared__ float Ws[32 * 257];   // [k][h]

    const int b   = blockIdx.y;
    const int t0  = blockIdx.x * 50;
    const int tid = threadIdx.x;
    const int it   = tid >> 5;       // 0..9  (t-group)
    const int lane = tid & 31;       // 0..31 (h-group) == warp lane
    const int tb = it * 5, hb = lane * 8;

    if (tid < 256) dhs[tid] = dh[b * 256 + tid];

    float acc[5][8];
    #pragma unroll
    for (int i = 0; i < 5; i++)
        #pragma unroll
        for (int j = 0; j < 8; j++) acc[i][j] = 0.f;

    const float* encb = enc + (size_t)b * Tn * H2;

    for (int kt = 0; kt < 512; kt += 32) {
        for (int i = tid; i < 50 * 32; i += 320) {
            int t = i >> 5, k = i & 31;
            Es[k * 51 + t] = encb[(size_t)(t0 + t) * 512 + kt + k];
        }
        for (int i = tid; i < 256 * 32; i += 320) {
            int h = i >> 5, k = i & 31;
            Ws[k * 257 + h] = Wc[(size_t)h * 512 + kt + k];
        }
        __syncthreads();
        #pragma unroll
        for (int k = 0; k < 32; k++) {
            float a[5], w[8];
            #pragma unroll
            for (int i = 0; i < 5; i++) a[i] = Es[k * 51 + tb + i];
            #pragma unroll
            for (int j = 0; j < 8; j++) w[j] = Ws[k * 257 + hb + j];
            #pragma unroll
            for (int i = 0; i < 5; i++)
                #pragma unroll
                for (int j = 0; j < 8; j++) acc[i][j] += a[i] * w[j];
        }
        __syncthreads();
    }

    float bias[8], dv[8];
    #pragma unroll
    for (int j = 0; j < 8; j++) { bias[j] = Wcb[hb + j]; dv[j] = dhs[hb + j]; }

    #pragma unroll
    for (int i = 0; i < 5; i++) {
        float s = 0.f;
        #pragma unroll
        for (int j = 0; j < 8; j++)
            s += tanhf(acc[i][j] + bias[j]) * dv[j];
        // warp reduce over the 32 h-groups (lanes)
        #pragma unroll
        for (int off = 16; off > 0; off >>= 1)
            s += __shfl_down_sync(0xffffffffu, s, off);
        if (lane == 0) {
            int t = t0 + tb + i;
            float sc = tanhf(s);
            if (encIdx[b * Tn + t] == 0) sc -= 10000.f;
            g_scorec[b * Tn + t] = sc;
        }
    }
}

// ---------------------------------------------------------------------------
// Kernel D: per-row softmax stats over concat[score_g(V), score_c(T)].
// ---------------------------------------------------------------------------
__global__ __launch_bounds__(256) void stats_kernel()
{
    __shared__ float red[256];
    const int b = blockIdx.x, tid = threadIdx.x;
    const int L = Vn + Tn;

    float m = -INFINITY;
    for (int i = tid; i < L; i += 256) {
        float v = (i < Vn) ? g_score[(size_t)b * Vn + i] : g_scorec[b * Tn + (i - Vn)];
        m = fmaxf(m, v);
    }
    red[tid] = m; __syncthreads();
    for (int s = 128; s > 0; s >>= 1) {
        if (tid < s) red[tid] = fmaxf(red[tid], red[tid + s]);
        __syncthreads();
    }
    float mx = red[0];
    __syncthreads();

    float sum = 0.f;
    for (int i = tid; i < L; i += 256) {
        float v = (i < Vn) ? g_score[(size_t)b * Vn + i] : g_scorec[b * Tn + (i - Vn)];
        sum += expf(v - mx);
    }
    red[tid] = sum; __syncthreads();
    for (int s = 128; s > 0; s >>= 1) {
        if (tid < s) red[tid] += red[tid + s];
        __syncthreads();
    }
    if (tid == 0) { g_max[b] = mx; g_invsum[b] = 1.f / red[0]; }
}

// ---------------------------------------------------------------------------
// Kernel E: prob_out base = [ prob_g (V) | 0.0001 (MAX_OOV) ].
// ---------------------------------------------------------------------------
__global__ __launch_bounds__(256) void probg_kernel(float* __restrict__ out)
{
    int idx = blockIdx.x * 256 + threadIdx.x;
    if (idx >= Bn * PV) return;
    int b = idx / PV, v = idx - b * PV;
    out[idx] = (v < Vn)
        ? expf(g_score[(size_t)b * Vn + v] - g_max[b]) * g_invsum[b]
        : 1e-4f;
}

// ---------------------------------------------------------------------------
// Kernel F: prob_c, scatter-add into prob_out, selective_read_new.
// One block per batch row.
// ---------------------------------------------------------------------------
__global__ __launch_bounds__(256) void final_kernel(
    const int* __restrict__ dec_in, const int* __restrict__ encIdx,
    const float* __restrict__ enc,
    float* __restrict__ prob_out, float* __restrict__ sel_out)
{
    __shared__ float pc[Tn];
    __shared__ float wt[Tn];
    __shared__ float norm;

    const int b = blockIdx.x, tid = threadIdx.x;
    const float mx = g_max[b], inv = g_invsum[b];
    const int dec = dec_in[b];

    if (tid < Tn) {
        float p = expf(g_scorec[b * Tn + tid] - mx) * inv;
        pc[tid] = p;
        wt[tid] = (encIdx[b * Tn + tid] == dec) ? 1.f : 0.f;
    }
    __syncthreads();
    if (tid == 0) {
        float t = 0.f;
        for (int i = 0; i < Tn; i++) t += wt[i];
        norm = (t > 1.f) ? 1.f / t : 1.f;
    }
    __syncthreads();
    float nf = norm;
    if (tid < Tn) {
        wt[tid] = wt[tid] * pc[tid] * nf;
        atomicAdd(&prob_out[(size_t)b * PV + encIdx[b * Tn + tid]], pc[tid]);
    }
    __syncthreads();

    const float* encb = enc + (size_t)b * Tn * H2;
    for (int e = tid; e < H2; e += 256) {
        float s = 0.f;
        #pragma unroll 4
        for (int t = 0; t < Tn; t++) s += wt[t] * encb[(size_t)t * H2 + e];
        sel_out[b * H2 + e] = s;
    }
}

// ---------------------------------------------------------------------------
extern "C" void kernel_launch(void* const* d_in, const int* in_sizes, int n_in,
                              void* d_out, int out_size)
{
    const int*   dec  = (const int*)d_in[0];
    const float* enc  = (const float*)d_in[1];
    const int*   eidx = (const int*)d_in[2];
    const float* prev = (const float*)d_in[3];
    const float* sel  = (const float*)d_in[4];
    const int si = (n_in >= 17) ? 1 : 0;          // is 'step' passed as input?
    const int* step = si ? (const int*)d_in[5] : nullptr;
    const float* emb = (const float*)d_in[5 + si];
    const float* Wih = (const float*)d_in[6 + si];
    const float* Whh = (const float*)d_in[7 + si];
    const float* bih = (const float*)d_in[8 + si];
    const float* bhh = (const float*)d_in[9 + si];
    const float* Wiw = (const float*)d_in[10 + si];
    const float* Wib = (const float*)d_in[11 + si];
    const float* Wgw = (const float*)d_in[12 + si];
    const float* Wgb = (const float*)d_in[13 + si];
    const float* Wcw = (const float*)d_in[14 + si];
    const float* Wcb = (const float*)d_in[15 + si];

    float* out    = (float*)d_out;
    float* prob   = out;                              // (B, 1, V+OOV)
    float* dh     = out + (size_t)Bn * PV;            // (B, H)
    float* selnew = dh + Bn * Hn;                     // (B, 1, 2H)

    gru_kernel<<<Bn, 256>>>(dec, enc, step, prev, sel, emb, Wih, Whh, bih, bhh,
                            Wiw, Wib, dh);
    scoreg_kernel<<<(Vn + 63) / 64, 256>>>(dh, Wgw, Wgb);
    dim3 gc(4, Bn);
    scorec_kernel<<<gc, 320>>>(enc, eidx, Wcw, Wcb, dh);
    stats_kernel<<<Bn, 256>>>();
    probg_kernel<<<(Bn * PV + 255) / 256, 256>>>(prob);
    final_kernel<<<Bn, 256>>>(dec, eidx, enc, prob, selnew);
}

// round 6
// speedup vs baseline: 2.2859x; 2.2859x over previous
#include <cuda_runtime.h>
#include <math.h>
#include <stdint.h>

#define Bn   128
#define Tn   200
#define Vn   50257
#define Hn   256
#define En   128
#define OOV  50
#define H2   512
#define XD   640
#define PV   (Vn + OOV)
#define NTILES 393          // ceil(Vn/128)
#define CTILES 400          // 25600/64

__device__ float g_score[(size_t)Bn * Vn];
__device__ float g_scorec[Bn * Tn];
__device__ float g_pm[Bn * NTILES];
__device__ float g_ps[Bn * NTILES];
__device__ float g_max[Bn];
__device__ float g_invsum[Bn];

// ============================ helpers =======================================
__device__ __forceinline__ uint32_t tf32_rna(float x) {
    uint32_t r;
    asm("cvt.rna.tf32.f32 %0, %1;" : "=r"(r) : "f"(x));
    return r;
}
__device__ __forceinline__ float ftanh(float x) {
    x = fminf(10.f, fmaxf(-10.f, x));
    float e = __expf(2.f * x);
    return __fdividef(e - 1.f, e + 1.f);
}
// m16n8k8 tf32 MMA (sm_80+ baseline instruction; assembles for sm_103)
__device__ __forceinline__ void mma_tf32(float c[4], const uint32_t a[4],
                                         const uint32_t b[2]) {
    asm volatile(
        "mma.sync.aligned.m16n8k8.row.col.f32.tf32.tf32.f32 "
        "{%0,%1,%2,%3}, {%4,%5,%6,%7}, {%8,%9}, {%0,%1,%2,%3};"
        : "+f"(c[0]), "+f"(c[1]), "+f"(c[2]), "+f"(c[3])
        : "r"(a[0]), "r"(a[1]), "r"(a[2]), "r"(a[3]), "r"(b[0]), "r"(b[1]));
}

// ---------------------------------------------------------------------------
// Kernel A: GRU cell. 4 batches per block (grid 32), 256 threads.
// ---------------------------------------------------------------------------
__global__ __launch_bounds__(256) void gru_kernel(
    const int* __restrict__ dec_in, const float* __restrict__ enc,
    const int* __restrict__ step,
    const float* __restrict__ prev_state, const float* __restrict__ sel,
    const float* __restrict__ emb,
    const float* __restrict__ W_ih, const float* __restrict__ W_hh,
    const float* __restrict__ b_ih, const float* __restrict__ b_hh,
    const float* __restrict__ Wi_w, const float* __restrict__ Wi_b,
    float* __restrict__ dh_out)
{
    __shared__ __align__(16) float xs[4][XD];
    __shared__ __align__(16) float hs[4][Hn];
    __shared__ __align__(16) float es[4][H2];

    const int b0  = blockIdx.x * 4;
    const int tid = threadIdx.x;
    const int stepv = step ? step[0] : 1;

    for (int i = tid; i < 4 * H2; i += 256) {
        int bb = i >> 9, v = i & 511;
        xs[bb][v] = stepv ? sel[(b0 + bb) * H2 + v] : 0.f;
    }
    for (int i = tid; i < 4 * En; i += 256) {
        int bb = i >> 7, v = i & 127;
        xs[bb][H2 + v] = emb[(size_t)dec_in[b0 + bb] * En + v];
    }
    if (stepv) {
        for (int i = tid; i < 4 * Hn; i += 256) {
            int bb = i >> 8, v = i & 255;
            hs[bb][v] = prev_state[(b0 + bb) * Hn + v];
        }
        __syncthreads();
    } else {
        for (int i = tid; i < 4 * H2; i += 256) {
            int bb = i >> 9, v = i & 511;
            es[bb][v] = enc[((size_t)(b0 + bb) * Tn + (Tn - 1)) * H2 + v];
        }
        __syncthreads();
        const int j = tid;
        const float4* wr = (const float4*)(Wi_w + (size_t)j * H2);
        float bj = Wi_b[j];
        float acc[4] = {bj, bj, bj, bj};
        for (int k = 0; k < H2 / 4; k++) {
            float4 w = wr[k];
            #pragma unroll
            for (int bb = 0; bb < 4; bb++) {
                float4 e = ((const float4*)es[bb])[k];
                acc[bb] += w.x * e.x + w.y * e.y + w.z * e.z + w.w * e.w;
            }
        }
        #pragma unroll
        for (int bb = 0; bb < 4; bb++) hs[bb][j] = acc[bb];
        __syncthreads();
    }

    const int j = tid;
    float gir[4], giz[4], gin[4], ghr[4], ghz[4], ghn[4];
    {
        float v0 = b_ih[j], v1 = b_ih[Hn + j], v2 = b_ih[2 * Hn + j];
        #pragma unroll
        for (int bb = 0; bb < 4; bb++) { gir[bb] = v0; giz[bb] = v1; gin[bb] = v2; }
        const float4* r0 = (const float4*)(W_ih + (size_t)j * XD);
        const float4* r1 = (const float4*)(W_ih + (size_t)(Hn + j) * XD);
        const float4* r2 = (const float4*)(W_ih + (size_t)(2 * Hn + j) * XD);
        for (int k = 0; k < XD / 4; k++) {
            float4 w0 = r0[k], w1 = r1[k], w2 = r2[k];
            #pragma unroll
            for (int bb = 0; bb < 4; bb++) {
                float4 x = ((const float4*)xs[bb])[k];
                gir[bb] += w0.x * x.x + w0.y * x.y + w0.z * x.z + w0.w * x.w;
                giz[bb] += w1.x * x.x + w1.y * x.y + w1.z * x.z + w1.w * x.w;
                gin[bb] += w2.x * x.x + w2.y * x.y + w2.z * x.z + w2.w * x.w;
            }
        }
    }
    {
        float v0 = b_hh[j], v1 = b_hh[Hn + j], v2 = b_hh[2 * Hn + j];
        #pragma unroll
        for (int bb = 0; bb < 4; bb++) { ghr[bb] = v0; ghz[bb] = v1; ghn[bb] = v2; }
        const float4* r0 = (const float4*)(W_hh + (size_t)j * Hn);
        const float4* r1 = (const float4*)(W_hh + (size_t)(Hn + j) * Hn);
        const float4* r2 = (const float4*)(W_hh + (size_t)(2 * Hn + j) * Hn);
        for (int k = 0; k < Hn / 4; k++) {
            float4 w0 = r0[k], w1 = r1[k], w2 = r2[k];
            #pragma unroll
            for (int bb = 0; bb < 4; bb++) {
                float4 x = ((const float4*)hs[bb])[k];
                ghr[bb] += w0.x * x.x + w0.y * x.y + w0.z * x.z + w0.w * x.w;
                ghz[bb] += w1.x * x.x + w1.y * x.y + w1.z * x.z + w1.w * x.w;
                ghn[bb] += w2.x * x.x + w2.y * x.y + w2.z * x.z + w2.w * x.w;
            }
        }
    }
    #pragma unroll
    for (int bb = 0; bb < 4; bb++) {
        float r = 1.f / (1.f + expf(-(gir[bb] + ghr[bb])));
        float z = 1.f / (1.f + expf(-(giz[bb] + ghz[bb])));
        float n = tanhf(gin[bb] + r * ghn[bb]);
        dh_out[(b0 + bb) * Hn + j] = (1.f - z) * n + z * hs[bb][j];
    }
}

// ---------------------------------------------------------------------------
// Kernel B: score_g via mma.sync tf32. Block 128x128xK256, warp 64x32.
// Epilogue: bias + softmax partials + coalesced staged stores.
// ---------------------------------------------------------------------------
__global__ __launch_bounds__(256) void scoreg_mma(
    const float* __restrict__ dh, const float* __restrict__ Wg,
    const float* __restrict__ Wgb)
{
    extern __shared__ __align__(16) float dyn[];
    float* As = dyn;                 // [128][68]
    float* Bs = dyn + 128 * 68;      // [128][68]
    __shared__ float biasS[128];

    const int tid  = threadIdx.x;
    const int wid  = tid >> 5, lane = tid & 31;
    const int warpM = wid >> 2, warpN = wid & 3;
    const int lr = lane >> 2, lc = lane & 3;
    const int v0 = blockIdx.x * 128;
    const int nvalid = (Vn - v0 < 128) ? (Vn - v0) : 128;

    if (tid < 128) {
        int vg = v0 + tid;
        biasS[tid] = (vg < Vn) ? Wgb[vg] : 0.f;
    }

    float acc[4][4][4];
    #pragma unroll
    for (int mi = 0; mi < 4; mi++)
        #pragma unroll
        for (int ni = 0; ni < 4; ni++)
            #pragma unroll
            for (int q = 0; q < 4; q++) acc[mi][ni][q] = 0.f;

    for (int kc = 0; kc < 4; kc++) {
        #pragma unroll
        for (int p = 0; p < 8; p++) {            // A = dh (128 x 64)
            int idx = tid + p * 256;
            int m = idx >> 4, c4 = (idx & 15) * 4;
            float4 v = *(const float4*)(dh + m * 256 + kc * 64 + c4);
            float* d = &As[m * 68 + c4];
            d[0] = __uint_as_float(tf32_rna(v.x));
            d[1] = __uint_as_float(tf32_rna(v.y));
            d[2] = __uint_as_float(tf32_rna(v.z));
            d[3] = __uint_as_float(tf32_rna(v.w));
        }
        #pragma unroll
        for (int p = 0; p < 8; p++) {            // B = Wg (128 x 64)
            int idx = tid + p * 256;
            int n = idx >> 4, c4 = (idx & 15) * 4;
            int vg = v0 + n;
            float4 v = (vg < Vn) ? *(const float4*)(Wg + (size_t)vg * 256 + kc * 64 + c4)
                                 : make_float4(0.f, 0.f, 0.f, 0.f);
            float* d = &Bs[n * 68 + c4];
            d[0] = __uint_as_float(tf32_rna(v.x));
            d[1] = __uint_as_float(tf32_rna(v.y));
            d[2] = __uint_as_float(tf32_rna(v.z));
            d[3] = __uint_as_float(tf32_rna(v.w));
        }
        __syncthreads();
        #pragma unroll
        for (int k0 = 0; k0 < 64; k0 += 8) {
            uint32_t af[4][4], bf[4][2];
            #pragma unroll
            for (int mi = 0; mi < 4; mi++) {
                int row = warpM * 64 + mi * 16 + lr;
                af[mi][0] = __float_as_uint(As[row * 68 + k0 + lc]);
                af[mi][1] = __float_as_uint(As[(row + 8) * 68 + k0 + lc]);
                af[mi][2] = __float_as_uint(As[row * 68 + k0 + 4 + lc]);
                af[mi][3] = __float_as_uint(As[(row + 8) * 68 + k0 + 4 + lc]);
            }
            #pragma unroll
            for (int ni = 0; ni < 4; ni++) {
                int n = warpN * 32 + ni * 8 + lr;
                bf[ni][0] = __float_as_uint(Bs[n * 68 + k0 + lc]);
                bf[ni][1] = __float_as_uint(Bs[n * 68 + k0 + 4 + lc]);
            }
            #pragma unroll
            for (int mi = 0; mi < 4; mi++)
                #pragma unroll
                for (int ni = 0; ni < 4; ni++)
                    mma_tf32(acc[mi][ni], af[mi], bf[ni]);
        }
        __syncthreads();
    }

    // stage results (bias added) into smem [128][132]
    float* stg = dyn;
    #pragma unroll
    for (int mi = 0; mi < 4; mi++) {
        int row = warpM * 64 + mi * 16 + lr;
        #pragma unroll
        for (int ni = 0; ni < 4; ni++) {
            int col = warpN * 32 + ni * 8 + 2 * lc;
            stg[row * 132 + col]           = acc[mi][ni][0] + biasS[col];
            stg[row * 132 + col + 1]       = acc[mi][ni][1] + biasS[col + 1];
            stg[(row + 8) * 132 + col]     = acc[mi][ni][2] + biasS[col];
            stg[(row + 8) * 132 + col + 1] = acc[mi][ni][3] + biasS[col + 1];
        }
    }
    __syncthreads();

    if (tid < 128) {                   // per-batch softmax partials
        const float* rowp = stg + tid * 132;
        float m = -INFINITY;
        for (int c = 0; c < nvalid; c++) m = fmaxf(m, rowp[c]);
        float s = 0.f;
        for (int c = 0; c < nvalid; c++) s += __expf(rowp[c] - m);
        g_pm[tid * NTILES + blockIdx.x] = m;
        g_ps[tid * NTILES + blockIdx.x] = s;
    }
    for (int i = tid; i < 128 * 128; i += 256) {
        int r = i >> 7, c = i & 127;
        if (c < nvalid) g_score[(size_t)r * Vn + v0 + c] = stg[r * 132 + c];
    }
}

// ---------------------------------------------------------------------------
// Kernel C: score_c via mma.sync tf32 over flattened enc (25600 x 512).
// Block 64x256xK512, warp 32x64. Epilogue: tanh(P+b).dh -> tanh -> mask.
// ---------------------------------------------------------------------------
__global__ __launch_bounds__(256) void scorec_mma(
    const float* __restrict__ enc, const int* __restrict__ encIdx,
    const float* __restrict__ Wc, const float* __restrict__ Wcb,
    const float* __restrict__ dh)
{
    extern __shared__ __align__(16) float dyn[];
    float* As = dyn;                 // [64][68]
    float* Bs = dyn + 64 * 68;       // [256][68]
    __shared__ float biasS[256];
    __shared__ float dh2[2][256];
    __shared__ float red[64][4];

    const int tid  = threadIdx.x;
    const int wid  = tid >> 5, lane = tid & 31;
    const int warpM = wid >> 2, warpN = wid & 3;
    const int lr = lane >> 2, lc = lane & 3;
    const int r0 = blockIdx.x * 64;
    const int b0 = r0 / Tn;
    const int b1 = (b0 + 1 < Bn) ? b0 + 1 : Bn - 1;

    biasS[tid] = Wcb[tid];
    for (int i = tid; i < 512; i += 256) {
        int w = i >> 8;
        dh2[w][i & 255] = dh[(w ? b1 : b0) * 256 + (i & 255)];
    }

    float acc[2][8][4];
    #pragma unroll
    for (int mi = 0; mi < 2; mi++)
        #pragma unroll
        for (int ni = 0; ni < 8; ni++)
            #pragma unroll
            for (int q = 0; q < 4; q++) acc[mi][ni][q] = 0.f;

    for (int kc = 0; kc < 8; kc++) {
        #pragma unroll
        for (int p = 0; p < 4; p++) {            // A = enc (64 x 64)
            int idx = tid + p * 256;
            int m = idx >> 4, c4 = (idx & 15) * 4;
            float4 v = *(const float4*)(enc + (size_t)(r0 + m) * 512 + kc * 64 + c4);
            float* d = &As[m * 68 + c4];
            d[0] = __uint_as_float(tf32_rna(v.x));
            d[1] = __uint_as_float(tf32_rna(v.y));
            d[2] = __uint_as_float(tf32_rna(v.z));
            d[3] = __uint_as_float(tf32_rna(v.w));
        }
        #pragma unroll
        for (int p = 0; p < 16; p++) {           // B = Wc (256 x 64)
            int idx = tid + p * 256;
            int n = idx >> 4, c4 = (idx & 15) * 4;
            float4 v = *(const float4*)(Wc + (size_t)n * 512 + kc * 64 + c4);
            float* d = &Bs[n * 68 + c4];
            d[0] = __uint_as_float(tf32_rna(v.x));
            d[1] = __uint_as_float(tf32_rna(v.y));
            d[2] = __uint_as_float(tf32_rna(v.z));
            d[3] = __uint_as_float(tf32_rna(v.w));
        }
        __syncthreads();
        #pragma unroll
        for (int k0 = 0; k0 < 64; k0 += 8) {
            uint32_t af[2][4], bf[8][2];
            #pragma unroll
            for (int mi = 0; mi < 2; mi++) {
                int row = warpM * 32 + mi * 16 + lr;
                af[mi][0] = __float_as_uint(As[row * 68 + k0 + lc]);
                af[mi][1] = __float_as_uint(As[(row + 8) * 68 + k0 + lc]);
                af[mi][2] = __float_as_uint(As[row * 68 + k0 + 4 + lc]);
                af[mi][3] = __float_as_uint(As[(row + 8) * 68 + k0 + 4 + lc]);
            }
            #pragma unroll
            for (int ni = 0; ni < 8; ni++) {
                int n = warpN * 64 + ni * 8 + lr;
                bf[ni][0] = __float_as_uint(Bs[n * 68 + k0 + lc]);
                bf[ni][1] = __float_as_uint(Bs[n * 68 + k0 + 4 + lc]);
            }
            #pragma unroll
            for (int mi = 0; mi < 2; mi++)
                #pragma unroll
                for (int ni = 0; ni < 8; ni++)
                    mma_tf32(acc[mi][ni], af[mi], bf[ni]);
        }
        __syncthreads();
    }

    // epilogue: per-row sum over this warp's 64 h-columns of tanh(v+b)*dh
    #pragma unroll
    for (int mi = 0; mi < 2; mi++) {
        int rowa = warpM * 32 + mi * 16 + lr;
        int rowb = rowa + 8;
        int ba = (r0 + rowa) / Tn - b0;
        int bb = (r0 + rowb) / Tn - b0;
        float pa = 0.f, pb = 0.f;
        #pragma unroll
        for (int ni = 0; ni < 8; ni++) {
            int col = warpN * 64 + ni * 8 + 2 * lc;
            float t0 = ftanh(acc[mi][ni][0] + biasS[col]);
            float t1 = ftanh(acc[mi][ni][1] + biasS[col + 1]);
            float t2 = ftanh(acc[mi][ni][2] + biasS[col]);
            float t3 = ftanh(acc[mi][ni][3] + biasS[col + 1]);
            pa += t0 * dh2[ba][col] + t1 * dh2[ba][col + 1];
            pb += t2 * dh2[bb][col] + t3 * dh2[bb][col + 1];
        }
        pa += __shfl_xor_sync(0xffffffffu, pa, 1);
        pa += __shfl_xor_sync(0xffffffffu, pa, 2);
        pb += __shfl_xor_sync(0xffffffffu, pb, 1);
        pb += __shfl_xor_sync(0xffffffffu, pb, 2);
        if (lc == 0) {
            red[rowa][warpN] = pa;
            red[rowb][warpN] = pb;
        }
    }
    __syncthreads();
    if (tid < 64) {
        float s = red[tid][0] + red[tid][1] + red[tid][2] + red[tid][3];
        float sc = ftanh(s);
        int gr = r0 + tid;
        if (encIdx[gr] == 0) sc -= 10000.f;
        g_scorec[gr] = sc;
    }
}

// ---------------------------------------------------------------------------
// Kernel D: combine per-tile softmax partials.
// ---------------------------------------------------------------------------
__global__ __launch_bounds__(256) void combine_kernel()
{
    __shared__ float red[256];
    const int b = blockIdx.x, tid = threadIdx.x;

    float m = -INFINITY;
    for (int i = tid; i < NTILES; i += 256) m = fmaxf(m, g_pm[b * NTILES + i]);
    for (int i = tid; i < Tn; i += 256)     m = fmaxf(m, g_scorec[b * Tn + i]);
    red[tid] = m; __syncthreads();
    for (int s = 128; s > 0; s >>= 1) {
        if (tid < s) red[tid] = fmaxf(red[tid], red[tid + s]);
        __syncthreads();
    }
    float mx = red[0];
    __syncthreads();

    float s = 0.f;
    for (int i = tid; i < NTILES; i += 256)
        s += g_ps[b * NTILES + i] * __expf(g_pm[b * NTILES + i] - mx);
    for (int i = tid; i < Tn; i += 256)
        s += __expf(g_scorec[b * Tn + i] - mx);
    red[tid] = s; __syncthreads();
    for (int k = 128; k > 0; k >>= 1) {
        if (tid < k) red[tid] += red[tid + k];
        __syncthreads();
    }
    if (tid == 0) { g_max[b] = mx; g_invsum[b] = 1.f / red[0]; }
}

// ---------------------------------------------------------------------------
// Kernel E: prob_out base = [ prob_g (V) | 1e-4 (OOV) ].
// ---------------------------------------------------------------------------
__global__ __launch_bounds__(256) void probg_kernel(float* __restrict__ out)
{
    int idx = blockIdx.x * 256 + threadIdx.x;
    if (idx >= Bn * PV) return;
    int b = idx / PV, v = idx - b * PV;
    out[idx] = (v < Vn)
        ? __expf(g_score[(size_t)b * Vn + v] - g_max[b]) * g_invsum[b]
        : 1e-4f;
}

// ---------------------------------------------------------------------------
// Kernel F: prob_c, scatter-add into prob_out, selective_read_new.
// ---------------------------------------------------------------------------
__global__ __launch_bounds__(256) void final_kernel(
    const int* __restrict__ dec_in, const int* __restrict__ encIdx,
    const float* __restrict__ enc,
    float* __restrict__ prob_out, float* __restrict__ sel_out)
{
    __shared__ float pc[Tn];
    __shared__ float wt[Tn];
    __shared__ float norm;

    const int b = blockIdx.x, tid = threadIdx.x;
    const float mx = g_max[b], inv = g_invsum[b];
    const int dec = dec_in[b];

    if (tid < Tn) {
        float p = __expf(g_scorec[b * Tn + tid] - mx) * inv;
        pc[tid] = p;
        wt[tid] = (encIdx[b * Tn + tid] == dec) ? 1.f : 0.f;
    }
    __syncthreads();
    if (tid == 0) {
        float t = 0.f;
        for (int i = 0; i < Tn; i++) t += wt[i];
        norm = (t > 1.f) ? 1.f / t : 1.f;
    }
    __syncthreads();
    float nf = norm;
    if (tid < Tn) {
        wt[tid] = wt[tid] * pc[tid] * nf;
        atomicAdd(&prob_out[(size_t)b * PV + encIdx[b * Tn + tid]], pc[tid]);
    }
    __syncthreads();

    const float* encb = enc + (size_t)b * Tn * H2;
    for (int e = tid; e < H2; e += 256) {
        float s = 0.f;
        #pragma unroll 4
        for (int t = 0; t < Tn; t++) s += wt[t] * encb[(size_t)t * H2 + e];
        sel_out[b * H2 + e] = s;
    }
}

// ---------------------------------------------------------------------------
extern "C" void kernel_launch(void* const* d_in, const int* in_sizes, int n_in,
                              void* d_out, int out_size)
{
    const int*   dec  = (const int*)d_in[0];
    const float* enc  = (const float*)d_in[1];
    const int*   eidx = (const int*)d_in[2];
    const float* prev = (const float*)d_in[3];
    const float* sel  = (const float*)d_in[4];
    const int si = (n_in >= 17) ? 1 : 0;
    const int* step = si ? (const int*)d_in[5] : nullptr;
    const float* emb = (const float*)d_in[5 + si];
    const float* Wih = (const float*)d_in[6 + si];
    const float* Whh = (const float*)d_in[7 + si];
    const float* bih = (const float*)d_in[8 + si];
    const float* bhh = (const float*)d_in[9 + si];
    const float* Wiw = (const float*)d_in[10 + si];
    const float* Wib = (const float*)d_in[11 + si];
    const float* Wgw = (const float*)d_in[12 + si];
    const float* Wgb = (const float*)d_in[13 + si];
    const float* Wcw = (const float*)d_in[14 + si];
    const float* Wcb = (const float*)d_in[15 + si];

    float* out    = (float*)d_out;
    float* prob   = out;                       // (B, 1, V+OOV)
    float* dh     = out + (size_t)Bn * PV;     // (B, H)
    float* selnew = dh + Bn * Hn;              // (B, 1, 2H)

    const int SMEM_G = 2 * 128 * 68 * 4;                 // 69632 B
    const int SMEM_C = (64 * 68 + 256 * 68) * 4;         // 87040 B
    cudaFuncSetAttribute(scoreg_mma, cudaFuncAttributeMaxDynamicSharedMemorySize, SMEM_G);
    cudaFuncSetAttribute(scorec_mma, cudaFuncAttributeMaxDynamicSharedMemorySize, SMEM_C);

    gru_kernel<<<Bn / 4, 256>>>(dec, enc, step, prev, sel, emb, Wih, Whh,
                                bih, bhh, Wiw, Wib, dh);
    scoreg_mma<<<NTILES, 256, SMEM_G>>>(dh, Wgw, Wgb);
    scorec_mma<<<CTILES, 256, SMEM_C>>>(enc, eidx, Wcw, Wcb, dh);
    combine_kernel<<<Bn, 256>>>();
    probg_kernel<<<(Bn * PV + 255) / 256, 256>>>(prob);
    final_kernel<<<Bn, 256>>>(dec, eidx, enc, prob, selnew);
}